// round 5
// baseline (speedup 1.0000x reference)
#include <cuda_runtime.h>
#include <cuda_bf16.h>
#include <cstdint>

#define NB 32
#define ND 64
#define NT 4096
#define NK 1024
#define NTOK (NB*NT)          // 131072 tokens
#define OUTQ (NB*ND*NT)       // 8388608 quantized elements

#define CBSTR8 144            // bytes per code row: [H(64) | M(64) | pad(16)]
#define CHUNK_CODES 128
#define NCHUNK (NK/CHUNK_CODES)                // 8
#define CHUNK_BYTES (CHUNK_CODES*CBSTR8)       // 18432
#define CHUNK_16B (CHUNK_BYTES/16)             // 1152
#define SCL_16B (CHUNK_CODES*4/16)             // 32

#define SX_STRIDE 68          // floats per dim row (conflict-free)
#define SMEM_SX_BYTES (64*SX_STRIDE*4)         // 17408
#define SMEM_CB0 SMEM_SX_BYTES                 // 17408
#define SMEM_CB1 (SMEM_CB0 + CHUNK_BYTES)      // 35840
#define SMEM_SCL0 (SMEM_CB1 + CHUNK_BYTES)     // 54272
#define SMEM_SCL1 (SMEM_SCL0 + 512)            // 54784
#define SMEM_TOTAL (SMEM_SCL1 + 512)           // 55296

#define TAUF 160.0f           // >= 2*hard error bound in dequant units -> exactness
#define GT_TPB 256
#define NPART 2048            // gather blocks (64 tokens each)

// Scratch (no allocations allowed)
__device__ int           g_idx[NTOK];
__device__ float         g_part[NPART];
__device__ unsigned char g_cb8[NK * CBSTR8];   // per-chunk-contiguous [H|M|pad] int8
__device__ float         g_scl[NK];            // per-code dequant scale

// ============================ helpers ============================
static __device__ __forceinline__ uint32_t smem_to_u32(const void* p) {
    uint32_t a;
    asm("{ .reg .u64 tmp; cvta.to.shared.u64 tmp, %1; cvt.u32.u64 %0, tmp; }" : "=r"(a) : "l"(p));
    return a;
}
static __device__ __forceinline__ void cp_async16(uint32_t dst, const void* src) {
    asm volatile("cp.async.cg.shared.global [%0], [%1], 16;" :: "r"(dst), "l"(src) : "memory");
}
static __device__ __forceinline__ void cp_commit() {
    asm volatile("cp.async.commit_group;" ::: "memory");
}
static __device__ __forceinline__ void cp_wait1() {
    asm volatile("cp.async.wait_group 1;" ::: "memory");
}
static __device__ __forceinline__ void cp_wait0() {
    asm volatile("cp.async.wait_group 0;" ::: "memory");
}
static __device__ __forceinline__ void ldmatrix_x4(uint32_t& r0, uint32_t& r1,
                                                   uint32_t& r2, uint32_t& r3, uint32_t a) {
    asm volatile("ldmatrix.sync.aligned.m8n8.x4.shared.b16 {%0,%1,%2,%3}, [%4];"
        : "=r"(r0), "=r"(r1), "=r"(r2), "=r"(r3) : "r"(a));
}
static __device__ __forceinline__ void mma_s8(int& c0, int& c1, int& c2, int& c3,
                                              uint32_t a0, uint32_t a1, uint32_t a2, uint32_t a3,
                                              uint32_t b0, uint32_t b1) {
    asm volatile("mma.sync.aligned.m16n8k32.row.col.s32.s8.s8.s32 "
        "{%0,%1,%2,%3}, {%4,%5,%6,%7}, {%8,%9}, {%0,%1,%2,%3};"
        : "+r"(c0), "+r"(c1), "+r"(c2), "+r"(c3)
        : "r"(a0), "r"(a1), "r"(a2), "r"(a3), "r"(b0), "r"(b1));
}
static __device__ __forceinline__ uint32_t pack4(int v0, int v1, int v2, int v3) {
    return (uint32_t)(v0 & 0xff) | ((uint32_t)(v1 & 0xff) << 8)
         | ((uint32_t)(v2 & 0xff) << 16) | ((uint32_t)v3 << 24);
}
// running top-2 update (ascending idx scan; first-max semantics)
static __device__ __forceinline__ void upd(float v, int idx, float& b, int& bi,
                                           float& s, int& si) {
    if (v > s) {
        if (v > b) { s = b; si = bi; b = v; bi = idx; }
        else       { s = v; si = idx; }
    }
}
// merge another top-2 into mine ((value desc, idx asc) priority)
static __device__ __forceinline__ void mrg(float& b, int& bi, float& s, int& si,
                                           float ob, int obi, float os, int osi) {
    if (ob > b || (ob == b && obi < bi)) {
        if (b > os || (b == os && bi < osi)) { s = b;  si = bi; }
        else                                 { s = os; si = osi; }
        b = ob; bi = obi;
    } else if (ob > s || (ob == s && obi < si)) {
        s = ob; si = obi;
    }
}

// ---------------------------------------------------------------------------
// Kernel 0: quantize codebook rows to 2-level int8 [H|M], per-code scale.
// v/s = H + M/252 + eps, |eps| <= 1/504, s = amax/126.
// ---------------------------------------------------------------------------
__global__ void vq_prep_kernel(const float* __restrict__ emb)
{
    int code = blockIdx.x * blockDim.x + threadIdx.x;
    if (code >= NK) return;
    const float* e = emb + (size_t)code * ND;
    float am = 1e-30f;
#pragma unroll 8
    for (int d = 0; d < ND; d++) am = fmaxf(am, fabsf(e[d]));
    float Q = 126.0f / am;
    unsigned char* row = g_cb8 + ((code >> 7) * CHUNK_CODES + (code & 127)) * (size_t)CBSTR8;
#pragma unroll 8
    for (int d = 0; d < ND; d++) {
        float t = e[d] * Q;
        int h = __float2int_rn(t);
        int m = __float2int_rn((t - (float)h) * 252.0f);
        row[d]      = (unsigned char)(h & 0xff);
        row[64 + d] = (unsigned char)(m & 0xff);
    }
    g_scl[code] = am / 126.0f;
}

// ---------------------------------------------------------------------------
// Kernel 1: IMMA int8 argmax. CTA = 64 tokens (8 warps x 8 tokens).
// score ~ s_k*(252*h.H + h.M + m.H); top-2 tracked; margin < TAUF (>= 2*err
// hard bound) triggers warp-cooperative exact fp32 rescan -> idx exact.
// ---------------------------------------------------------------------------
__global__ void __launch_bounds__(256, 2) vq_mma_argmax_kernel(
        const float* __restrict__ in, const float* __restrict__ emb,
        float* __restrict__ out)
{
    extern __shared__ float sx[];          // [64 dims][SX_STRIDE] fp32, then code bufs
    const uint32_t sbase = smem_to_u32(sx);
    const int tid  = threadIdx.x;
    const int lane = tid & 31;
    const int w    = tid >> 5;
    const int gid  = lane >> 2;
    const int tig  = lane & 3;

    const int n0 = blockIdx.x * 64;
    const int b  = n0 >> 12;
    const int t0 = n0 & (NT - 1);

    // stage x tile [64 d][64 t] fp32, coalesced
    {
        const float4* src = reinterpret_cast<const float4*>(in + (size_t)b * ND * NT + t0);
#pragma unroll
        for (int k = 0; k < 4; k++) {
            int i = tid + k * 256;
            int d = i >> 4, q = i & 15;
            float4 v = src[(size_t)d * (NT / 4) + q];
            *reinterpret_cast<float4*>(sx + d * SX_STRIDE + q * 4) = v;
        }
    }
    // preload code chunk 0 (+ its scales)
    for (int i = tid; i < CHUNK_16B + SCL_16B; i += 256) {
        if (i < CHUNK_16B) cp_async16(sbase + SMEM_CB0 + i * 16, g_cb8 + i * 16);
        else cp_async16(sbase + SMEM_SCL0 + (i - CHUNK_16B) * 16,
                        (const char*)g_scl + (i - CHUNK_16B) * 16);
    }
    cp_commit();
    __syncthreads();   // sx visible

    // build token-side int8 fragments (B operand): token = w*8 + gid
    const int tok = w * 8 + gid;
    uint32_t bh[4], bm[4];
    {
        float xv[16];
        float am = 1e-30f;
#pragma unroll
        for (int j = 0; j < 4; j++)
#pragma unroll
            for (int i = 0; i < 4; i++) {
                float v = sx[(16 * j + 4 * tig + i) * SX_STRIDE + tok];
                xv[4 * j + i] = v;
                am = fmaxf(am, fabsf(v));
            }
        am = fmaxf(am, __shfl_xor_sync(0xffffffffu, am, 1));
        am = fmaxf(am, __shfl_xor_sync(0xffffffffu, am, 2));
        float Q = 126.0f / am;
#pragma unroll
        for (int j = 0; j < 4; j++) {
            int h[4], m[4];
#pragma unroll
            for (int i = 0; i < 4; i++) {
                float t = xv[4 * j + i] * Q;
                h[i] = __float2int_rn(t);
                m[i] = __float2int_rn((t - (float)h[i]) * 252.0f);
            }
            bh[j] = pack4(h[0], h[1], h[2], h[3]);
            bm[j] = pack4(m[0], m[1], m[2], m[3]);
        }
    }

    float bestv[2] = { -3.0e38f, -3.0e38f }, secv[2] = { -3.0e38f, -3.0e38f };
    int   besti[2] = { 0, 0 },               seci[2] = { 0, 0 };

    const uint32_t lmoff = (uint32_t)((lane & 15) * CBSTR8 + ((lane >> 4) & 1) * 16);

    for (int c = 0; c < NCHUNK; c++) {
        const uint32_t bufo = (c & 1) ? SMEM_CB1 : SMEM_CB0;
        const uint32_t sclo = (c & 1) ? SMEM_SCL1 : SMEM_SCL0;
        if (c + 1 < NCHUNK) {
            const uint32_t nbufo = (c & 1) ? SMEM_CB0 : SMEM_CB1;
            const uint32_t nsclo = (c & 1) ? SMEM_SCL0 : SMEM_SCL1;
            const char* srcc = (const char*)g_cb8 + (size_t)(c + 1) * CHUNK_BYTES;
            const char* srcs = (const char*)g_scl + (size_t)(c + 1) * CHUNK_CODES * 4;
            for (int i = tid; i < CHUNK_16B + SCL_16B; i += 256) {
                if (i < CHUNK_16B) cp_async16(sbase + nbufo + i * 16, srcc + i * 16);
                else cp_async16(sbase + nsclo + (i - CHUNK_16B) * 16, srcs + (i - CHUNK_16B) * 16);
            }
            cp_commit();
            cp_wait1();
        } else {
            cp_wait0();
        }
        __syncthreads();

        const float* scl = reinterpret_cast<const float*>(
            reinterpret_cast<const char*>(sx) + sclo);

#pragma unroll 2
        for (int mt = 0; mt < 8; mt++) {
            uint32_t lm = sbase + bufo + lmoff + (uint32_t)(mt * 16 * CBSTR8);
            uint32_t AH1[4], AH2[4], AM1[4], AM2[4];
            ldmatrix_x4(AH1[0], AH1[1], AH1[2], AH1[3], lm);        // H k0-31
            ldmatrix_x4(AH2[0], AH2[1], AH2[2], AH2[3], lm + 32);   // H k32-63
            ldmatrix_x4(AM1[0], AM1[1], AM1[2], AM1[3], lm + 64);   // M k0-31
            ldmatrix_x4(AM2[0], AM2[1], AM2[2], AM2[3], lm + 96);   // M k32-63

            int p[4]  = {0, 0, 0, 0};   // h.H
            int qa[4] = {0, 0, 0, 0};   // h.M
            int qb[4] = {0, 0, 0, 0};   // m.H
            mma_s8(p[0], p[1], p[2], p[3],  AH1[0], AH1[1], AH1[2], AH1[3], bh[0], bh[1]);
            mma_s8(qa[0], qa[1], qa[2], qa[3], AM1[0], AM1[1], AM1[2], AM1[3], bh[0], bh[1]);
            mma_s8(qb[0], qb[1], qb[2], qb[3], AH1[0], AH1[1], AH1[2], AH1[3], bm[0], bm[1]);
            mma_s8(p[0], p[1], p[2], p[3],  AH2[0], AH2[1], AH2[2], AH2[3], bh[2], bh[3]);
            mma_s8(qa[0], qa[1], qa[2], qa[3], AM2[0], AM2[1], AM2[2], AM2[3], bh[2], bh[3]);
            mma_s8(qb[0], qb[1], qb[2], qb[3], AH2[0], AH2[1], AH2[2], AH2[3], bm[2], bm[3]);

            const int ib = c * CHUNK_CODES + mt * 16;
            float sk0 = scl[mt * 16 + gid];
            float sk1 = scl[mt * 16 + gid + 8];
            float f0 = (float)(252 * p[0] + qa[0] + qb[0]) * sk0;
            float f1 = (float)(252 * p[1] + qa[1] + qb[1]) * sk0;
            float f2 = (float)(252 * p[2] + qa[2] + qb[2]) * sk1;
            float f3 = (float)(252 * p[3] + qa[3] + qb[3]) * sk1;
            upd(f0, ib + gid,     bestv[0], besti[0], secv[0], seci[0]);
            upd(f1, ib + gid,     bestv[1], besti[1], secv[1], seci[1]);
            upd(f2, ib + gid + 8, bestv[0], besti[0], secv[0], seci[0]);
            upd(f3, ib + gid + 8, bestv[1], besti[1], secv[1], seci[1]);
        }
        __syncthreads();
    }

    // butterfly merge of top-2 across the 8 row-groups (lanes differing in bits 2..4)
#pragma unroll
    for (int off = 4; off <= 16; off <<= 1) {
#pragma unroll
        for (int col = 0; col < 2; col++) {
            float ob  = __shfl_xor_sync(0xffffffffu, bestv[col], off);
            int   obi = __shfl_xor_sync(0xffffffffu, besti[col], off);
            float os  = __shfl_xor_sync(0xffffffffu, secv[col],  off);
            int   osi = __shfl_xor_sync(0xffffffffu, seci[col],  off);
            mrg(bestv[col], besti[col], secv[col], seci[col], ob, obi, os, osi);
        }
    }

    // near-tie rescue: full exact fp32 rescan, warp-cooperative (uniform control)
    unsigned m0 = __ballot_sync(0xffffffffu, (lane < 4) && (bestv[0] - secv[0] < TAUF)) & 0xFu;
    unsigned m1 = __ballot_sync(0xffffffffu, (lane < 4) && (bestv[1] - secv[1] < TAUF)) & 0xFu;
    if (m0 | m1) {
        for (int l = 0; l < 4; l++) {
#pragma unroll
            for (int col = 0; col < 2; col++) {
                unsigned mm = col ? m1 : m0;
                if ((mm >> l) & 1u) {
                    const int ts = w * 8 + 2 * l + col;   // token slot in block-tile
                    float bb = -3.0e38f; int bi = 0;
                    for (int cc = lane; cc < NK; cc += 32) {
                        const float* e = emb + (size_t)cc * ND;
                        float a0 = 0.f, a1 = 0.f, a2 = 0.f, a3 = 0.f;
#pragma unroll
                        for (int d = 0; d < ND; d += 4) {
                            a0 = fmaf(sx[d * SX_STRIDE + ts],       e[d],     a0);
                            a1 = fmaf(sx[(d + 1) * SX_STRIDE + ts], e[d + 1], a1);
                            a2 = fmaf(sx[(d + 2) * SX_STRIDE + ts], e[d + 2], a2);
                            a3 = fmaf(sx[(d + 3) * SX_STRIDE + ts], e[d + 3], a3);
                        }
                        float v = (a0 + a1) + (a2 + a3);
                        if (v > bb) { bb = v; bi = cc; }
                    }
#pragma unroll
                    for (int off = 16; off; off >>= 1) {
                        float ov = __shfl_xor_sync(0xffffffffu, bb, off);
                        int   oi = __shfl_xor_sync(0xffffffffu, bi, off);
                        if (ov > bb || (ov == bb && oi < bi)) { bb = ov; bi = oi; }
                    }
                    if (lane == l) besti[col] = bi;
                }
            }
        }
    }

    if (lane < 4) {
        const int n = n0 + w * 8 + 2 * lane;
        g_idx[n]     = besti[0];
        g_idx[n + 1] = besti[1];
        out[OUTQ + 2 + n]     = (float)besti[0];
        out[OUTQ + 2 + n + 1] = (float)besti[1];
    }
}

// ---------------------------------------------------------------------------
// Kernel 2: gather quantized output + loss partials, smem-staged so every
// gmem access is coalesced. Block = 64 tokens of one batch.
// commitment_loss == codebook_loss forward == mean((flat - emb_unnorm[idx])^2)
// ---------------------------------------------------------------------------
__global__ void __launch_bounds__(GT_TPB) vq_gather_loss_kernel(
        const float* __restrict__ in, const float* __restrict__ emb,
        const float* __restrict__ embu, float* __restrict__ out)
{
    __shared__ int   sidx[64];
    __shared__ float sq[64 * 65];
    __shared__ float su[64 * 65];

    const int tid = threadIdx.x;
    const int n0  = blockIdx.x * 64;
    const int b   = n0 >> 12;
    const int t0  = n0 & (NT - 1);

    if (tid < 64) sidx[tid] = g_idx[n0 + tid];
    __syncthreads();

    {
        const int tok = tid >> 2;
        const int q   = tid & 3;
        const int code = sidx[tok];
        const float4* e4 = reinterpret_cast<const float4*>(emb  + (size_t)code * ND);
        const float4* u4 = reinterpret_cast<const float4*>(embu + (size_t)code * ND);
#pragma unroll
        for (int j = 0; j < 4; j++) {
            float4 f = e4[q * 4 + j];
            float4 u = u4[q * 4 + j];
            int base = tok * 65 + q * 16 + j * 4;
            sq[base] = f.x; sq[base+1] = f.y; sq[base+2] = f.z; sq[base+3] = f.w;
            su[base] = u.x; su[base+1] = u.y; su[base+2] = u.z; su[base+3] = u.w;
        }
    }
    __syncthreads();

    const int d  = tid >> 2;
    const int j0 = (tid & 3) * 16;
    const size_t gbase = (size_t)b * ND * NT + (size_t)d * NT + t0 + j0;
    float lsum = 0.f;
#pragma unroll
    for (int i = 0; i < 16; i++) {
        float xi = in[gbase + i];
        out[gbase + i] = sq[(j0 + i) * 65 + d];
        float df = xi - su[(j0 + i) * 65 + d];
        lsum += df * df;
    }

#pragma unroll
    for (int o = 16; o; o >>= 1) lsum += __shfl_xor_sync(0xffffffffu, lsum, o);
    __shared__ float ws[GT_TPB / 32];
    if ((tid & 31) == 0) ws[tid >> 5] = lsum;
    __syncthreads();
    if (tid < 32) {
        float v = (tid < GT_TPB / 32) ? ws[tid] : 0.f;
#pragma unroll
        for (int o = 4; o; o >>= 1) v += __shfl_xor_sync(0xffffffffu, v, o);
        if (tid == 0) g_part[blockIdx.x] = v;
    }
}

// ---------------------------------------------------------------------------
// Kernel 3: final loss reduction (double precision), write scalars.
// ---------------------------------------------------------------------------
__global__ void vq_finalize_kernel(float* __restrict__ out)
{
    __shared__ double sd[256];
    double s = 0.0;
    for (int i = threadIdx.x; i < NPART; i += 256) s += (double)g_part[i];
    sd[threadIdx.x] = s;
    __syncthreads();
    for (int o = 128; o; o >>= 1) {
        if (threadIdx.x < o) sd[threadIdx.x] += sd[threadIdx.x + o];
        __syncthreads();
    }
    if (threadIdx.x == 0) {
        float m = (float)(sd[0] / (double)OUTQ);
        out[OUTQ]     = m;   // commitment_loss
        out[OUTQ + 1] = m;   // codebook_loss (numerically identical forward)
    }
}

extern "C" void kernel_launch(void* const* d_in, const int* in_sizes, int n_in,
                              void* d_out, int out_size) {
    const float* in   = (const float*)d_in[0];   // [32, 64, 4096] fp32
    const float* emb  = (const float*)d_in[1];   // [1024, 64] fp32 (pre-normalized)
    const float* embu = (const float*)d_in[2];   // [1024, 64] fp32
    float* out = (float*)d_out;

    static int configured = 0;
    if (!configured) {
        cudaFuncSetAttribute(vq_mma_argmax_kernel,
                             cudaFuncAttributeMaxDynamicSharedMemorySize, SMEM_TOTAL);
        configured = 1;
    }

    vq_prep_kernel<<<NK / 256, 256>>>(emb);
    vq_mma_argmax_kernel<<<NTOK / 64, 256, SMEM_TOTAL>>>(in, emb, out);
    vq_gather_loss_kernel<<<NPART, GT_TPB>>>(in, emb, embu, out);
    vq_finalize_kernel<<<1, 256>>>(out);
}

// round 6
// speedup vs baseline: 4.3594x; 4.3594x over previous
#include <cuda_runtime.h>
#include <cuda_bf16.h>
#include <cstdint>

#define NB 32
#define ND 64
#define NT 4096
#define NK 1024
#define NTOK (NB*NT)          // 131072 tokens
#define OUTQ (NB*ND*NT)       // 8388608 quantized elements

#define CBSTRIDE 136          // ushorts per code row: [H(64) | M(64) | pad(8)] = 272B
#define CHUNK_CODES 128
#define NCHUNK (NK/CHUNK_CODES)       // 8
#define CHUNK_BYTES (CHUNK_CODES*CBSTRIDE*2)   // 34816
#define CHUNK_16B (CHUNK_BYTES/16)             // 2176

#define SX_STRIDE 68          // floats per dim row (conflict-free)
#define SMEM_SX_BYTES (64*SX_STRIDE*4)         // 17408
#define SMEM_CB0 SMEM_SX_BYTES
#define SMEM_CB1 (SMEM_CB0 + CHUNK_BYTES)
#define SMEM_TOTAL (SMEM_CB1 + CHUNK_BYTES)    // 87040

#define TAU 1e-3f
#define GT_TPB 256
#define NPART 2048            // gather blocks (64 tokens each)

// Scratch (no allocations allowed)
__device__ int            g_idx[NTOK];
__device__ float          g_part[NPART];
__device__ unsigned short g_cb[NK * CBSTRIDE];   // codebook split [H|M] bf16, padded rows

// ============================ helpers ============================
static __device__ __forceinline__ uint32_t smem_to_u32(const void* p) {
    uint32_t a;
    asm("{ .reg .u64 tmp; cvta.to.shared.u64 tmp, %1; cvt.u32.u64 %0, tmp; }" : "=r"(a) : "l"(p));
    return a;
}
static __device__ __forceinline__ void cp_async16(uint32_t dst, const void* src) {
    asm volatile("cp.async.cg.shared.global [%0], [%1], 16;" :: "r"(dst), "l"(src) : "memory");
}
static __device__ __forceinline__ void cp_commit() {
    asm volatile("cp.async.commit_group;" ::: "memory");
}
static __device__ __forceinline__ void cp_wait1() {
    asm volatile("cp.async.wait_group 1;" ::: "memory");
}
static __device__ __forceinline__ void cp_wait0() {
    asm volatile("cp.async.wait_group 0;" ::: "memory");
}
static __device__ __forceinline__ void ldmatrix_x4(uint32_t& r0, uint32_t& r1,
                                                   uint32_t& r2, uint32_t& r3, uint32_t a) {
    asm volatile("ldmatrix.sync.aligned.m8n8.x4.shared.b16 {%0,%1,%2,%3}, [%4];"
        : "=r"(r0), "=r"(r1), "=r"(r2), "=r"(r3) : "r"(a));
}
static __device__ __forceinline__ void mma_bf16(float* c,
                                                uint32_t a0, uint32_t a1, uint32_t a2, uint32_t a3,
                                                uint32_t b0, uint32_t b1) {
    asm volatile("mma.sync.aligned.m16n8k16.row.col.f32.bf16.bf16.f32 "
        "{%0,%1,%2,%3}, {%4,%5,%6,%7}, {%8,%9}, {%0,%1,%2,%3};"
        : "+f"(c[0]), "+f"(c[1]), "+f"(c[2]), "+f"(c[3])
        : "r"(a0), "r"(a1), "r"(a2), "r"(a3), "r"(b0), "r"(b1));
}
static __device__ __forceinline__ uint32_t packbf(__nv_bfloat16 a, __nv_bfloat16 b) {
    return (uint32_t)__bfloat16_as_ushort(a) | ((uint32_t)__bfloat16_as_ushort(b) << 16);
}
// running top-2 update (ascending idx scan; first-max semantics)
static __device__ __forceinline__ void upd(float v, int idx, float& b, int& bi,
                                           float& s, int& si) {
    if (v > s) {
        if (v > b) { s = b; si = bi; b = v; bi = idx; }
        else       { s = v; si = idx; }
    }
}
// merge another top-2 into mine ((value desc, idx asc) priority)
static __device__ __forceinline__ void mrg(float& b, int& bi, float& s, int& si,
                                           float ob, int obi, float os, int osi) {
    if (ob > b || (ob == b && obi < bi)) {
        if (b > os || (b == os && bi < osi)) { s = b;  si = bi; }
        else                                 { s = os; si = osi; }
        b = ob; bi = obi;
    } else if (ob > s || (ob == s && obi < si)) {
        s = ob; si = obi;
    }
}

// ---------------------------------------------------------------------------
// Kernel 0: split codebook rows into [H | M] bf16, padded stride.
// H = bf16(v); M = bf16(v - H).
// ---------------------------------------------------------------------------
__global__ void vq_prep_kernel(const float* __restrict__ emb)
{
    int i = blockIdx.x * blockDim.x + threadIdx.x;
    if (i >= NK * ND) return;
    int code = i >> 6, d = i & 63;
    float v = emb[i];
    __nv_bfloat16 h = __float2bfloat16_rn(v);
    float r = v - __bfloat162float(h);
    __nv_bfloat16 m = __float2bfloat16_rn(r);
    g_cb[code * CBSTRIDE + d]      = __bfloat16_as_ushort(h);
    g_cb[code * CBSTRIDE + 64 + d] = __bfloat16_as_ushort(m);
}

// ---------------------------------------------------------------------------
// Kernel 1: mma.sync bf16 argmax. CTA = 64 tokens (8 warps x 8 tokens).
// scores = x.e via hH + hM + mH (err <= ~8e-5); per code-tile PAIR we keep 6
// independent accumulator chains (3 products x 2 tiles) interleaved at
// k-step granularity -> dependency distance 6 HMMAs, keeps tensor pipe full.
// Near-ties (margin < TAU) -> warp-cooperative exact fp32 rescan.
// ---------------------------------------------------------------------------
__global__ void __launch_bounds__(256, 2) vq_mma_argmax_kernel(
        const float* __restrict__ in, const float* __restrict__ emb,
        float* __restrict__ out)
{
    extern __shared__ float sx[];          // [64 dims][SX_STRIDE] fp32, then code bufs
    const uint32_t sbase = smem_to_u32(sx);
    const int tid  = threadIdx.x;
    const int lane = tid & 31;
    const int w    = tid >> 5;
    const int gid  = lane >> 2;
    const int tig  = lane & 3;

    const int n0 = blockIdx.x * 64;
    const int b  = n0 >> 12;
    const int t0 = n0 & (NT - 1);

    // stage x tile [64 d][64 t] fp32, coalesced
    {
        const float4* src = reinterpret_cast<const float4*>(in + (size_t)b * ND * NT + t0);
#pragma unroll
        for (int k = 0; k < 4; k++) {
            int i = tid + k * 256;
            int d = i >> 4, q = i & 15;
            float4 v = src[(size_t)d * (NT / 4) + q];
            *reinterpret_cast<float4*>(sx + d * SX_STRIDE + q * 4) = v;
        }
    }
    // preload code chunk 0
    for (int i = tid; i < CHUNK_16B; i += 256)
        cp_async16(sbase + SMEM_CB0 + i * 16, (const char*)g_cb + i * 16);
    cp_commit();
    __syncthreads();   // sx visible

    // build token-side fragments (B operand): token = w*8 + gid
    const int tok = w * 8 + gid;
    uint32_t bh[8], bm[8];
#pragma unroll
    for (int j = 0; j < 4; j++) {
        int d0 = j * 16 + 2 * tig;
        float v0 = sx[d0 * SX_STRIDE + tok];
        float v1 = sx[(d0 + 1) * SX_STRIDE + tok];
        float v2 = sx[(d0 + 8) * SX_STRIDE + tok];
        float v3 = sx[(d0 + 9) * SX_STRIDE + tok];
        __nv_bfloat16 h0 = __float2bfloat16_rn(v0), h1 = __float2bfloat16_rn(v1);
        __nv_bfloat16 h2 = __float2bfloat16_rn(v2), h3 = __float2bfloat16_rn(v3);
        bh[2*j]   = packbf(h0, h1);
        bh[2*j+1] = packbf(h2, h3);
        bm[2*j]   = packbf(__float2bfloat16_rn(v0 - __bfloat162float(h0)),
                           __float2bfloat16_rn(v1 - __bfloat162float(h1)));
        bm[2*j+1] = packbf(__float2bfloat16_rn(v2 - __bfloat162float(h2)),
                           __float2bfloat16_rn(v3 - __bfloat162float(h3)));
    }

    float bestv[2] = { -3.0e38f, -3.0e38f }, secv[2] = { -3.0e38f, -3.0e38f };
    int   besti[2] = { 0, 0 },               seci[2] = { 0, 0 };

    const uint32_t lmbase = sbase + (uint32_t)((lane & 15) * (CBSTRIDE * 2) + ((lane >> 4) * 16));

    for (int c = 0; c < NCHUNK; c++) {
        const uint32_t bufo = (c & 1) ? SMEM_CB1 : SMEM_CB0;
        if (c + 1 < NCHUNK) {
            const uint32_t nbufo = (c & 1) ? SMEM_CB0 : SMEM_CB1;
            const char* src = (const char*)g_cb + (size_t)(c + 1) * CHUNK_BYTES;
            for (int i = tid; i < CHUNK_16B; i += 256)
                cp_async16(sbase + nbufo + i * 16, src + i * 16);
            cp_commit();
            cp_wait1();
        } else {
            cp_wait0();
        }
        __syncthreads();

        // 4 iterations, each processing a PAIR of 16-code tiles
#pragma unroll 1
        for (int mt2 = 0; mt2 < 4; mt2++) {
            const uint32_t lma = lmbase + bufo + (uint32_t)((2 * mt2)     * 16 * CBSTRIDE * 2);
            const uint32_t lmb = lmbase + bufo + (uint32_t)((2 * mt2 + 1) * 16 * CBSTRIDE * 2);

            float pa[4] = {0,0,0,0}, qa[4] = {0,0,0,0}, ra[4] = {0,0,0,0};   // tile a: hH, hM, mH
            float pb[4] = {0,0,0,0}, qb[4] = {0,0,0,0}, rb[4] = {0,0,0,0};   // tile b

#pragma unroll
            for (int jj = 0; jj < 4; jj++) {
                uint32_t AHa[4], AMa[4], AHb[4], AMb[4];
                ldmatrix_x4(AHa[0], AHa[1], AHa[2], AHa[3], lma + jj * 32);
                ldmatrix_x4(AMa[0], AMa[1], AMa[2], AMa[3], lma + 128 + jj * 32);
                ldmatrix_x4(AHb[0], AHb[1], AHb[2], AHb[3], lmb + jj * 32);
                ldmatrix_x4(AMb[0], AMb[1], AMb[2], AMb[3], lmb + 128 + jj * 32);
                // 6 independent chains, each advanced once per k-step
                mma_bf16(pa, AHa[0], AHa[1], AHa[2], AHa[3], bh[2*jj], bh[2*jj+1]);
                mma_bf16(pb, AHb[0], AHb[1], AHb[2], AHb[3], bh[2*jj], bh[2*jj+1]);
                mma_bf16(qa, AMa[0], AMa[1], AMa[2], AMa[3], bh[2*jj], bh[2*jj+1]);
                mma_bf16(qb, AMb[0], AMb[1], AMb[2], AMb[3], bh[2*jj], bh[2*jj+1]);
                mma_bf16(ra, AHa[0], AHa[1], AHa[2], AHa[3], bm[2*jj], bm[2*jj+1]);
                mma_bf16(rb, AHb[0], AHb[1], AHb[2], AHb[3], bm[2*jj], bm[2*jj+1]);
            }

            const int iba = c * CHUNK_CODES + 2 * mt2 * 16;
            const int ibb = iba + 16;
            float fa0 = pa[0] + qa[0] + ra[0];
            float fa1 = pa[1] + qa[1] + ra[1];
            float fa2 = pa[2] + qa[2] + ra[2];
            float fa3 = pa[3] + qa[3] + ra[3];
            float fb0 = pb[0] + qb[0] + rb[0];
            float fb1 = pb[1] + qb[1] + rb[1];
            float fb2 = pb[2] + qb[2] + rb[2];
            float fb3 = pb[3] + qb[3] + rb[3];
            upd(fa0, iba + gid,     bestv[0], besti[0], secv[0], seci[0]);
            upd(fa1, iba + gid,     bestv[1], besti[1], secv[1], seci[1]);
            upd(fa2, iba + gid + 8, bestv[0], besti[0], secv[0], seci[0]);
            upd(fa3, iba + gid + 8, bestv[1], besti[1], secv[1], seci[1]);
            upd(fb0, ibb + gid,     bestv[0], besti[0], secv[0], seci[0]);
            upd(fb1, ibb + gid,     bestv[1], besti[1], secv[1], seci[1]);
            upd(fb2, ibb + gid + 8, bestv[0], besti[0], secv[0], seci[0]);
            upd(fb3, ibb + gid + 8, bestv[1], besti[1], secv[1], seci[1]);
        }
        __syncthreads();
    }

    // butterfly merge of top-2 across the 8 row-groups (lanes differing in bits 2..4)
#pragma unroll
    for (int off = 4; off <= 16; off <<= 1) {
#pragma unroll
        for (int col = 0; col < 2; col++) {
            float ob  = __shfl_xor_sync(0xffffffffu, bestv[col], off);
            int   obi = __shfl_xor_sync(0xffffffffu, besti[col], off);
            float os  = __shfl_xor_sync(0xffffffffu, secv[col],  off);
            int   osi = __shfl_xor_sync(0xffffffffu, seci[col],  off);
            mrg(bestv[col], besti[col], secv[col], seci[col], ob, obi, os, osi);
        }
    }

    // near-tie rescue: full exact fp32 rescan, warp-cooperative (uniform control)
    unsigned m0 = __ballot_sync(0xffffffffu, (lane < 4) && (bestv[0] - secv[0] < TAU)) & 0xFu;
    unsigned m1 = __ballot_sync(0xffffffffu, (lane < 4) && (bestv[1] - secv[1] < TAU)) & 0xFu;
    if (m0 | m1) {
        for (int l = 0; l < 4; l++) {
#pragma unroll
            for (int col = 0; col < 2; col++) {
                unsigned mm = col ? m1 : m0;
                if ((mm >> l) & 1u) {
                    const int ts = w * 8 + 2 * l + col;   // token slot in block-tile
                    float bb = -3.0e38f; int bi = 0;
                    for (int cc = lane; cc < NK; cc += 32) {
                        const float* e = emb + (size_t)cc * ND;
                        float a0 = 0.f, a1 = 0.f, a2 = 0.f, a3 = 0.f;
#pragma unroll
                        for (int d = 0; d < ND; d += 4) {
                            a0 = fmaf(sx[d * SX_STRIDE + ts],       e[d],     a0);
                            a1 = fmaf(sx[(d + 1) * SX_STRIDE + ts], e[d + 1], a1);
                            a2 = fmaf(sx[(d + 2) * SX_STRIDE + ts], e[d + 2], a2);
                            a3 = fmaf(sx[(d + 3) * SX_STRIDE + ts], e[d + 3], a3);
                        }
                        float v = (a0 + a1) + (a2 + a3);
                        if (v > bb) { bb = v; bi = cc; }
                    }
#pragma unroll
                    for (int off = 16; off; off >>= 1) {
                        float ov = __shfl_xor_sync(0xffffffffu, bb, off);
                        int   oi = __shfl_xor_sync(0xffffffffu, bi, off);
                        if (ov > bb || (ov == bb && oi < bi)) { bb = ov; bi = oi; }
                    }
                    if (lane == l) besti[col] = bi;
                }
            }
        }
    }

    if (lane < 4) {
        const int n = n0 + w * 8 + 2 * lane;
        g_idx[n]     = besti[0];
        g_idx[n + 1] = besti[1];
        out[OUTQ + 2 + n]     = (float)besti[0];
        out[OUTQ + 2 + n + 1] = (float)besti[1];
    }
}

// ---------------------------------------------------------------------------
// Kernel 2: gather quantized output + loss partials, smem-staged so every
// gmem access is coalesced. Block = 64 tokens of one batch.
// commitment_loss == codebook_loss forward == mean((flat - emb_unnorm[idx])^2)
// ---------------------------------------------------------------------------
__global__ void __launch_bounds__(GT_TPB) vq_gather_loss_kernel(
        const float* __restrict__ in, const float* __restrict__ emb,
        const float* __restrict__ embu, float* __restrict__ out)
{
    __shared__ int   sidx[64];
    __shared__ float sq[64 * 65];
    __shared__ float su[64 * 65];

    const int tid = threadIdx.x;
    const int n0  = blockIdx.x * 64;
    const int b   = n0 >> 12;
    const int t0  = n0 & (NT - 1);

    if (tid < 64) sidx[tid] = g_idx[n0 + tid];
    __syncthreads();

    {
        const int tok = tid >> 2;
        const int q   = tid & 3;
        const int code = sidx[tok];
        const float4* e4 = reinterpret_cast<const float4*>(emb  + (size_t)code * ND);
        const float4* u4 = reinterpret_cast<const float4*>(embu + (size_t)code * ND);
#pragma unroll
        for (int j = 0; j < 4; j++) {
            float4 f = e4[q * 4 + j];
            float4 u = u4[q * 4 + j];
            int base = tok * 65 + q * 16 + j * 4;
            sq[base] = f.x; sq[base+1] = f.y; sq[base+2] = f.z; sq[base+3] = f.w;
            su[base] = u.x; su[base+1] = u.y; su[base+2] = u.z; su[base+3] = u.w;
        }
    }
    __syncthreads();

    const int d  = tid >> 2;
    const int j0 = (tid & 3) * 16;
    const size_t gbase = (size_t)b * ND * NT + (size_t)d * NT + t0 + j0;
    float lsum = 0.f;
#pragma unroll
    for (int i = 0; i < 16; i++) {
        float xi = in[gbase + i];
        out[gbase + i] = sq[(j0 + i) * 65 + d];
        float df = xi - su[(j0 + i) * 65 + d];
        lsum += df * df;
    }

#pragma unroll
    for (int o = 16; o; o >>= 1) lsum += __shfl_xor_sync(0xffffffffu, lsum, o);
    __shared__ float ws[GT_TPB / 32];
    if ((tid & 31) == 0) ws[tid >> 5] = lsum;
    __syncthreads();
    if (tid < 32) {
        float v = (tid < GT_TPB / 32) ? ws[tid] : 0.f;
#pragma unroll
        for (int o = 4; o; o >>= 1) v += __shfl_xor_sync(0xffffffffu, v, o);
        if (tid == 0) g_part[blockIdx.x] = v;
    }
}

// ---------------------------------------------------------------------------
// Kernel 3: final loss reduction (double precision), write scalars.
// ---------------------------------------------------------------------------
__global__ void vq_finalize_kernel(float* __restrict__ out)
{
    __shared__ double sd[256];
    double s = 0.0;
    for (int i = threadIdx.x; i < NPART; i += 256) s += (double)g_part[i];
    sd[threadIdx.x] = s;
    __syncthreads();
    for (int o = 128; o; o >>= 1) {
        if (threadIdx.x < o) sd[threadIdx.x] += sd[threadIdx.x + o];
        __syncthreads();
    }
    if (threadIdx.x == 0) {
        float m = (float)(sd[0] / (double)OUTQ);
        out[OUTQ]     = m;   // commitment_loss
        out[OUTQ + 1] = m;   // codebook_loss (numerically identical forward)
    }
}

extern "C" void kernel_launch(void* const* d_in, const int* in_sizes, int n_in,
                              void* d_out, int out_size) {
    const float* in   = (const float*)d_in[0];   // [32, 64, 4096] fp32
    const float* emb  = (const float*)d_in[1];   // [1024, 64] fp32 (pre-normalized)
    const float* embu = (const float*)d_in[2];   // [1024, 64] fp32
    float* out = (float*)d_out;

    static int configured = 0;
    if (!configured) {
        cudaFuncSetAttribute(vq_mma_argmax_kernel,
                             cudaFuncAttributeMaxDynamicSharedMemorySize, SMEM_TOTAL);
        configured = 1;
    }

    vq_prep_kernel<<<(NK * ND) / 256, 256>>>(emb);
    vq_mma_argmax_kernel<<<NTOK / 64, 256, SMEM_TOTAL>>>(in, emb, out);
    vq_gather_loss_kernel<<<NPART, GT_TPB>>>(in, emb, embu, out);
    vq_finalize_kernel<<<1, 256>>>(out);
}